// round 14
// baseline (speedup 1.0000x reference)
#include <cuda_runtime.h>
#include <math_constants.h>

// Problem shape
#define BB 8
#define HH 3
#define PP 4096
#define NPTS (BB * PP)
#define CH 256                   // chunk size (both I and J side)
#define NCH (PP / CH)            // 16 chunks per batch
#define NSLOT (CH / 2)           // 128 packed J-slots
#define TP 128                   // threads per block (4 warps)
#define BLKB (NCH * (NCH + 1) / 2)   // 136 triangular blocks per batch
#define NBLK 128

// per-(head,point) min as uint bits of nonneg float; reset to 0x7F7F7F7F
__device__ unsigned int g_minbits[HH * NPTS];
__device__ float g_partial[NBLK];

typedef unsigned long long u64;

// ---- f32x2 helpers ---------------------------------------------------------
__device__ __forceinline__ u64 pack2(float lo, float hi) {
    u64 d;
    asm("mov.b64 %0, {%1, %2};" : "=l"(d) : "f"(lo), "f"(hi));
    return d;
}
__device__ __forceinline__ u64 fma2(u64 a, u64 b, u64 c) {
    u64 d;
    asm("fma.rn.f32x2 %0, %1, %2, %3;" : "=l"(d) : "l"(a), "l"(b), "l"(c));
    return d;
}
__device__ __forceinline__ u64 add2(u64 a, u64 b) {
    u64 d;
    asm("add.rn.f32x2 %0, %1, %2;" : "=l"(d) : "l"(a), "l"(b));
    return d;
}
__device__ __forceinline__ void unpack2(u64 t, float& lo, float& hi) {
    asm("mov.b64 {%0, %1}, %2;" : "=f"(lo), "=f"(hi) : "l"(t));
}

// normalized plane normals + offset for batch b
__device__ __forceinline__ void load_normals(const float* __restrict__ planes,
                                             int b, float nx[HH], float ny[HH],
                                             float nz[HH], float nc[HH]) {
#pragma unroll
    for (int h = 0; h < HH; h++) {
        const float* pl = planes + (b * HH + h) * 4;
        float x = pl[0], y = pl[1], z = pl[2];
        float nn = x * x + y * y + z * z;
        float inv = rsqrtf(nn);
        inv = inv * (1.5f - 0.5f * nn * inv * inv);
        nx[h] = x * inv; ny[h] = y * inv; nz[h] = z * inv; nc[h] = pl[3];
    }
}

// ---------------------------------------------------------------------------
// Symmetric chamfer. Block = (chunk ci, chunk cj), ci<=cj, 256 pts each.
// J-chunk register-resident: lane owns 4 packed slots + 24 J-min registers.
// I-chunk staged in smem (duplicated-pair constants); warp w covers I-points
// [w*64, w*64+64) in 2 groups of 32; at step r lane processes I-point
// (lane+r)&31 of the group -> distinct I loads + distinct sImin RMW slots.
// v(p,q) = w_q + w_p - 2 p.q + 4 d_p d_q   (= |p - reflect_h(q)|^2, exact).
// ---------------------------------------------------------------------------
__global__ __launch_bounds__(TP)
void chamfer_kernel(const float* __restrict__ planes,
                    const float* __restrict__ pts) {
    __shared__ u64   sJ[7][NSLOT];     // J staging: 7 KB
    __shared__ u64   sIc[7][CH];       // I constants (dup pairs): 14 KB
    __shared__ float sImin[HH][CH];    // I-side mins: 3 KB
    // J-merge reuses sIc after main loop: [warp][lane][24] floats (12 KB)
    float* sJm = (float*)&sIc[0][0];

    const int t    = threadIdx.x;
    const int lane = t & 31;
    const int w    = t >> 5;
    const int b    = blockIdx.z;

    // triangular decode: (ci, cj) with ci <= cj
    int f = blockIdx.x, ci = 0;
    while (f >= NCH - ci) { f -= NCH - ci; ci++; }
    const int cj = ci + f;

    float nx[HH], ny[HH], nz[HH], nc[HH];
    load_normals(planes, b, nx, ny, nz, nc);

    // ---- stage J-chunk (one slot = 2 points per thread) ----
    {
        const float* q = pts + (b * PP + cj * CH + 2 * t) * 3;
        float x0 = q[0], y0 = q[1], z0 = q[2];
        float x1 = q[3], y1 = q[4], z1 = q[5];
        sJ[0][t] = pack2(x0, x1);
        sJ[1][t] = pack2(y0, y1);
        sJ[2][t] = pack2(z0, z1);
        sJ[3][t] = pack2(x0*x0 + y0*y0 + z0*z0, x1*x1 + y1*y1 + z1*z1);
#pragma unroll
        for (int h = 0; h < HH; h++) {
            float d0 = 2.f * (nx[h] * x0 + ny[h] * y0 + nz[h] * z0 + nc[h]);
            float d1 = 2.f * (nx[h] * x1 + ny[h] * y1 + nz[h] * z1 + nc[h]);
            sJ[4 + h][t] = pack2(d0, d1);
        }
    }

    // ---- stage I-chunk constants (2 points per thread, dup pairs) ----
#pragma unroll
    for (int r = 0; r < 2; r++) {
        const int i = r * TP + t;
        const float* P = pts + (b * PP + ci * CH + i) * 3;
        float ax = P[0], ay = P[1], az = P[2];
        sIc[0][i] = pack2(-2.f * ax, -2.f * ax);
        sIc[1][i] = pack2(-2.f * ay, -2.f * ay);
        sIc[2][i] = pack2(-2.f * az, -2.f * az);
        float wp = ax * ax + ay * ay + az * az;
        sIc[3][i] = pack2(wp, wp);
#pragma unroll
        for (int h = 0; h < HH; h++) {
            float e = 2.f * (nx[h] * ax + ny[h] * ay + nz[h] * az + nc[h]);
            sIc[4 + h][i] = pack2(e, e);
        }
    }
    // init I-min buffer
#pragma unroll
    for (int r = 0; r < (HH * CH) / TP; r++)
        (&sImin[0][0])[r * TP + t] = CUDART_INF_F;

    __syncthreads();

    // ---- load lane's 4 permanent J slots into registers ----
    u64 jX[4], jY[4], jZ[4], jW[4], jD0[4], jD1[4], jD2[4];
    float jm0a[4], jm0b[4], jm1a[4], jm1b[4], jm2a[4], jm2b[4];
#pragma unroll
    for (int s = 0; s < 4; s++) {
        const int slot = s * 32 + lane;
        jX[s]  = sJ[0][slot]; jY[s]  = sJ[1][slot]; jZ[s] = sJ[2][slot];
        jW[s]  = sJ[3][slot];
        jD0[s] = sJ[4][slot]; jD1[s] = sJ[5][slot]; jD2[s] = sJ[6][slot];
        jm0a[s] = jm0b[s] = CUDART_INF_F;
        jm1a[s] = jm1b[s] = CUDART_INF_F;
        jm2a[s] = jm2b[s] = CUDART_INF_F;
    }

    // ---- main loop: warp w covers I-points [w*64, w*64+64) ----
#pragma unroll
    for (int g = 0; g < 2; g++) {
        const int gbase = w * 64 + g * 32;
        for (int r = 0; r < 32; r++) {
            const int i = gbase + ((lane + r) & 31);
            const u64 MX = sIc[0][i], MY = sIc[1][i], MZ = sIc[2][i];
            const u64 WP = sIc[3][i];
            const u64 E0 = sIc[4][i], E1 = sIc[5][i], E2 = sIc[6][i];

            float i0 = CUDART_INF_F, i1 = CUDART_INF_F, i2 = CUDART_INF_F;
#pragma unroll
            for (int s = 0; s < 4; s++) {
                u64 acc = fma2(MX, jX[s], add2(jW[s], WP));
                acc = fma2(MY, jY[s], acc);
                acc = fma2(MZ, jZ[s], acc);
                u64 v0 = fma2(E0, jD0[s], acc);
                u64 v1 = fma2(E1, jD1[s], acc);
                u64 v2 = fma2(E2, jD2[s], acc);
                float a0, b0, a1, b1, a2, b2;
                unpack2(v0, a0, b0);
                unpack2(v1, a1, b1);
                unpack2(v2, a2, b2);
                // J-side register mins
                jm0a[s] = fminf(jm0a[s], a0);  jm0b[s] = fminf(jm0b[s], b0);
                jm1a[s] = fminf(jm1a[s], a1);  jm1b[s] = fminf(jm1b[s], b1);
                jm2a[s] = fminf(jm2a[s], a2);  jm2b[s] = fminf(jm2b[s], b2);
                // I-side tree
                i0 = fminf(i0, fminf(a0, b0));
                i1 = fminf(i1, fminf(a1, b1));
                i2 = fminf(i2, fminf(a2, b2));
            }
            // I-min RMW (distinct i per lane this step)
            sImin[0][i] = fminf(sImin[0][i], i0);
            sImin[1][i] = fminf(sImin[1][i], i1);
            sImin[2][i] = fminf(sImin[2][i], i2);
            __syncwarp();
        }
    }

    __syncthreads();

    // ---- I-side epilogue: 2 points per thread ----
#pragma unroll
    for (int r = 0; r < 2; r++) {
        const int i = r * TP + t;
        const int idx = b * PP + ci * CH + i;
        atomicMin(&g_minbits[0 * NPTS + idx],
                  __float_as_uint(fmaxf(sImin[0][i], 0.f)));
        atomicMin(&g_minbits[1 * NPTS + idx],
                  __float_as_uint(fmaxf(sImin[1][i], 0.f)));
        atomicMin(&g_minbits[2 * NPTS + idx],
                  __float_as_uint(fmaxf(sImin[2][i], 0.f)));
    }

    // ---- J-side: dump per-warp partials (reuse sIc), merge, atomicMin ----
    {
        float* dst = sJm + (w * 32 + lane) * 24;
#pragma unroll
        for (int s = 0; s < 4; s++) {
            dst[s * 6 + 0] = jm0a[s]; dst[s * 6 + 1] = jm0b[s];
            dst[s * 6 + 2] = jm1a[s]; dst[s * 6 + 3] = jm1b[s];
            dst[s * 6 + 4] = jm2a[s]; dst[s * 6 + 5] = jm2b[s];
        }
    }
    __syncthreads();

    // thread t merges slot t = s*32+l across the 4 warps
    {
        const int s = t >> 5, l = t & 31;
        const int j0 = b * PP + cj * CH + 2 * (s * 32 + l);
#pragma unroll
        for (int i = 0; i < 6; i++) {
            const int off = l * 24 + s * 6 + i;
            float m = fminf(fminf(sJm[(0 * 32) * 24 + off],
                                  sJm[(1 * 32) * 24 + off]),
                            fminf(sJm[(2 * 32) * 24 + off],
                                  sJm[(3 * 32) * 24 + off]));
            const int head = i >> 1, half = i & 1;
            atomicMin(&g_minbits[head * NPTS + j0 + half],
                      __float_as_uint(fmaxf(m, 0.f)));
        }
    }
}

// ---------------------------------------------------------------------------
__global__ __launch_bounds__(256)
void combine_kernel() {
    __shared__ float red[256];
    const int i = blockIdx.x * 256 + threadIdx.x;

    float s = __uint_as_float(g_minbits[0 * NPTS + i])
            + __uint_as_float(g_minbits[1 * NPTS + i])
            + __uint_as_float(g_minbits[2 * NPTS + i]);

    red[threadIdx.x] = s;
    __syncthreads();
#pragma unroll
    for (int off = 128; off > 0; off >>= 1) {
        if (threadIdx.x < off) red[threadIdx.x] += red[threadIdx.x + off];
        __syncthreads();
    }
    if (threadIdx.x == 0) g_partial[blockIdx.x] = red[0];
}

__global__ __launch_bounds__(128)
void finalize_kernel(const float* __restrict__ planes,
                     float* __restrict__ out) {
    __shared__ float red[128];
    __shared__ float regs[BB];
    const int t = threadIdx.x;

    red[t] = g_partial[t];
    __syncthreads();
#pragma unroll
    for (int off = 64; off > 0; off >>= 1) {
        if (t < off) red[t] += red[t + off];
        __syncthreads();
    }

    if (t < BB) {
        float nx[HH], ny[HH], nz[HH], nc[HH];
        load_normals(planes, t, nx, ny, nz, nc);
        float acc = 0.0f;
#pragma unroll
        for (int i = 0; i < HH; i++)
#pragma unroll
            for (int j = 0; j < HH; j++) {
                float g = nx[i] * nx[j] + ny[i] * ny[j] + nz[i] * nz[j]
                        - (i == j ? 1.0f : 0.0f);
                acc += g * g;
            }
        regs[t] = sqrtf(acc);
    }
    __syncthreads();

    if (t == 0) {
        float reg = 0.0f;
#pragma unroll
        for (int b = 0; b < BB; b++) reg += regs[b];
        float refl = 2.0f * red[0] / (float)(BB * PP);  // cham_x == cham_y
        out[0] = refl + 25.0f * reg;
    }
}

// ---------------------------------------------------------------------------
extern "C" void kernel_launch(void* const* d_in, const int* in_sizes, int n_in,
                              void* d_out, int out_size) {
    const float* planes = (const float*)d_in[0];   // (8, 3, 4)
    const float* pts    = (const float*)d_in[1];   // (8, 4096, 3)
    // d_in[2], d_in[3] unused by the reference.

    void* mb = nullptr;
    cudaGetSymbolAddress(&mb, g_minbits);
    cudaMemsetAsync(mb, 0x7F, (size_t)HH * NPTS * sizeof(unsigned int));

    dim3 grid(BLKB, 1, BB);   // 136 x 8 = 1088 blocks
    chamfer_kernel<<<grid, TP>>>(planes, pts);

    combine_kernel<<<NBLK, 256>>>();
    finalize_kernel<<<1, 128>>>(planes, (float*)d_out);
}